// round 2
// baseline (speedup 1.0000x reference)
#include <cuda_runtime.h>

// ---------------------------------------------------------------------------
// DyNet2D: pooled routing -> softmax over 3 experts -> per-sample mixed 3x3
// kernel -> reflect-pad conv. B=16, C_in=C_out=16, H=W=512.
//
// Launch plan (graph-capturable, no allocs):
//   1) pool_kernel: 1024 blocks, partial sums of x over each (b,c,quarter)
//   2) mix_kernel : 1 block; finishes pooling, softmax routing, mixes expert
//                   kernels into g_wmix[b][ic][tap][oc] (oc contiguous)
//   3) conv_kernel: tiled direct conv, FMA-bound baseline
// ---------------------------------------------------------------------------

#define HW (512 * 512)            // 262144 per (b,c) plane

__device__ float g_partial[1024];           // (b*16+c)*4 + quarter
__device__ float g_wmix[16 * 2304];         // [b][ic][tap][oc], 16*16*9*16

// ------------------------------ 1) pooling --------------------------------
__global__ void pool_kernel(const float* __restrict__ x) {
    const int blk = blockIdx.x;           // bc*4 + q
    const int bc  = blk >> 2;
    const int q   = blk & 3;
    const float4* p = reinterpret_cast<const float4*>(x + (size_t)bc * HW + (size_t)q * 65536);
    float s = 0.0f;
    #pragma unroll 4
    for (int i = threadIdx.x; i < 16384; i += 256) {
        float4 v = p[i];
        s += (v.x + v.y) + (v.z + v.w);
    }
    #pragma unroll
    for (int o = 16; o > 0; o >>= 1) s += __shfl_down_sync(0xffffffffu, s, o);
    __shared__ float ws[8];
    if ((threadIdx.x & 31) == 0) ws[threadIdx.x >> 5] = s;
    __syncthreads();
    if (threadIdx.x == 0) {
        float t = 0.0f;
        #pragma unroll
        for (int i = 0; i < 8; i++) t += ws[i];
        g_partial[blk] = t;
    }
}

// --------------------- 2) routing softmax + kernel mix --------------------
__global__ void mix_kernel(const float* __restrict__ w_experts,  // [3][16][16][3][3]
                           const float* __restrict__ fc_w,       // [3][16]
                           const float* __restrict__ fc_b) {     // [3]
    __shared__ float pooled_s[256];   // [b][c]
    __shared__ float r_s[16][3];      // routing
    const int tid = threadIdx.x;

    pooled_s[tid] = (g_partial[tid * 4 + 0] + g_partial[tid * 4 + 1] +
                     g_partial[tid * 4 + 2] + g_partial[tid * 4 + 3]) * (1.0f / (float)HW);
    __syncthreads();

    if (tid < 16) {
        float lg[3];
        #pragma unroll
        for (int e = 0; e < 3; e++) {
            float a = fc_b[e];
            #pragma unroll
            for (int c = 0; c < 16; c++) a += pooled_s[tid * 16 + c] * fc_w[e * 16 + c];
            lg[e] = a;
        }
        float m = fmaxf(lg[0], fmaxf(lg[1], lg[2]));
        float ex0 = expf(lg[0] - m), ex1 = expf(lg[1] - m), ex2 = expf(lg[2] - m);
        float inv = 1.0f / (ex0 + ex1 + ex2);
        r_s[tid][0] = ex0 * inv;
        r_s[tid][1] = ex1 * inv;
        r_s[tid][2] = ex2 * inv;
    }
    __syncthreads();

    // g_wmix[b][c][tap][oc] = sum_e r[b][e] * w_experts[e][oc][c][tap]
    for (int i = tid; i < 36864; i += 256) {
        int b    = i / 2304;
        int rem  = i - b * 2304;
        int c    = rem / 144;
        int rem2 = rem - c * 144;
        int tap  = rem2 >> 4;
        int oc   = rem2 & 15;
        float v = 0.0f;
        #pragma unroll
        for (int e = 0; e < 3; e++)
            v += r_s[b][e] * w_experts[((e * 16 + oc) * 16 + c) * 9 + tap];
        g_wmix[i] = v;
    }
}

// ------------------------------ 3) conv -----------------------------------
// Tile: 64 (x) by 16 (y) outputs, all 16 input channels in SMEM.
// SMEM input: [c][18][68] (stride 68 keeps rows 16B aligned for LDS.128).
// Weights: [c][tap][oc] (oc contiguous -> broadcast LDS.128 per 4 oc).
// Each of 256 threads: 4 adjacent pixels (tx..tx+3) x 16 oc -> 64 fp32 accs.
__global__ void __launch_bounds__(256, 2)
conv_kernel(const float* __restrict__ x, const float* __restrict__ bias,
            float* __restrict__ out) {
    extern __shared__ float smem[];
    float* in_s = smem;                 // 16 * 1224 = 19584 floats
    float* w_s  = smem + 19584;         // 2304 floats
    float* b_s  = w_s + 2304;           // 16 floats

    const int tid = threadIdx.x;
    const int b   = blockIdx.z;
    const int x0  = blockIdx.x * 64;
    const int y0  = blockIdx.y * 16;

    // weights + bias
    for (int i = tid; i < 2304; i += 256) w_s[i] = g_wmix[b * 2304 + i];
    if (tid < 16) b_s[tid] = bias[tid];

    // input tile with reflect halo: smem col s <-> global x = x0 + s - 1
    const float* xb = x + (size_t)b * 16 * HW;
    for (int i = tid; i < 19008; i += 256) {       // 16 * 18 * 66
        int c   = i / 1188;
        int rem = i - c * 1188;
        int row = rem / 66;
        int col = rem - row * 66;
        int gy = y0 + row - 1; gy = gy < 0 ? -gy : (gy > 511 ? 1022 - gy : gy);
        int gx = x0 + col - 1; gx = gx < 0 ? -gx : (gx > 511 ? 1022 - gx : gx);
        in_s[c * 1224 + row * 68 + col] = xb[(c << 18) + (gy << 9) + gx];
    }
    __syncthreads();

    const int tx = (tid & 15) << 2;     // 0,4,...,60
    const int ty = tid >> 4;            // 0..15

    float4 acc[16];
    #pragma unroll
    for (int oc = 0; oc < 16; oc++) {
        float bv = b_s[oc];
        acc[oc] = make_float4(bv, bv, bv, bv);
    }

    const float* ip = in_s + ty * 68 + tx;

    #pragma unroll 1
    for (int c = 0; c < 16; c++) {
        float r[3][6];
        #pragma unroll
        for (int dy = 0; dy < 3; dy++) {
            const float* rp = ip + c * 1224 + dy * 68;
            float4 v4 = *reinterpret_cast<const float4*>(rp);
            float2 v2 = *reinterpret_cast<const float2*>(rp + 4);
            r[dy][0] = v4.x; r[dy][1] = v4.y; r[dy][2] = v4.z; r[dy][3] = v4.w;
            r[dy][4] = v2.x; r[dy][5] = v2.y;
        }
        const float* wc = w_s + c * 144;
        #pragma unroll
        for (int dy = 0; dy < 3; dy++) {
            #pragma unroll
            for (int dx = 0; dx < 3; dx++) {
                const float* wt = wc + (dy * 3 + dx) * 16;
                const float p0 = r[dy][dx + 0];
                const float p1 = r[dy][dx + 1];
                const float p2 = r[dy][dx + 2];
                const float p3 = r[dy][dx + 3];
                #pragma unroll
                for (int g = 0; g < 4; g++) {
                    float4 w = *reinterpret_cast<const float4*>(wt + g * 4);
                    acc[g*4+0].x += p0 * w.x; acc[g*4+0].y += p1 * w.x;
                    acc[g*4+0].z += p2 * w.x; acc[g*4+0].w += p3 * w.x;
                    acc[g*4+1].x += p0 * w.y; acc[g*4+1].y += p1 * w.y;
                    acc[g*4+1].z += p2 * w.y; acc[g*4+1].w += p3 * w.y;
                    acc[g*4+2].x += p0 * w.z; acc[g*4+2].y += p1 * w.z;
                    acc[g*4+2].z += p2 * w.z; acc[g*4+2].w += p3 * w.z;
                    acc[g*4+3].x += p0 * w.w; acc[g*4+3].y += p1 * w.w;
                    acc[g*4+3].z += p2 * w.w; acc[g*4+3].w += p3 * w.w;
                }
            }
        }
    }

    float* op = out + (size_t)(b * 16) * HW + ((y0 + ty) << 9) + x0 + tx;
    #pragma unroll
    for (int oc = 0; oc < 16; oc++)
        *reinterpret_cast<float4*>(op + ((size_t)oc << 18)) = acc[oc];
}

// ---------------------------------------------------------------------------
extern "C" void kernel_launch(void* const* d_in, const int* in_sizes, int n_in,
                              void* d_out, int out_size) {
    const float* x         = (const float*)d_in[0];   // [16,16,512,512]
    const float* w_experts = (const float*)d_in[1];   // [3,16,16,3,3]
    const float* bias      = (const float*)d_in[2];   // [16]
    const float* fc_w      = (const float*)d_in[3];   // [3,16]
    const float* fc_b      = (const float*)d_in[4];   // [3]
    float* out = (float*)d_out;

    const int smem_bytes = (19584 + 2304 + 16) * 4;   // 87616
    cudaFuncSetAttribute(conv_kernel, cudaFuncAttributeMaxDynamicSharedMemorySize, smem_bytes);

    pool_kernel<<<1024, 256>>>(x);
    mix_kernel<<<1, 256>>>(w_experts, fc_w, fc_b);
    conv_kernel<<<dim3(8, 32, 16), 256, smem_bytes>>>(x, bias, out);
}

// round 3
// speedup vs baseline: 1.0469x; 1.0469x over previous
#include <cuda_runtime.h>

// ---------------------------------------------------------------------------
// DyNet2D: pooled routing -> softmax over 3 experts -> per-sample mixed 3x3
// kernel -> reflect-pad conv. B=16, C_in=C_out=16, H=W=512.
//
// R2: conv inner loop rewritten with packed fma.rn.f32x2 (FFMA2).
// Accumulator lanes = (oc, oc+1) pairs so weights load as 64-bit SMEM words
// with no packing; broadcast pixel is duplicated via mov.b64 {p,p}.
// ---------------------------------------------------------------------------

#define HW (512 * 512)

__device__ float g_partial[1024];           // (b*16+c)*4 + quarter
__device__ float g_wmix[16 * 2304];         // [b][ic][tap][oc]

// ------------------------------ 1) pooling --------------------------------
__global__ void pool_kernel(const float* __restrict__ x) {
    const int blk = blockIdx.x;
    const int bc  = blk >> 2;
    const int q   = blk & 3;
    const float4* p = reinterpret_cast<const float4*>(x + (size_t)bc * HW + (size_t)q * 65536);
    float s = 0.0f;
    #pragma unroll 4
    for (int i = threadIdx.x; i < 16384; i += 256) {
        float4 v = p[i];
        s += (v.x + v.y) + (v.z + v.w);
    }
    #pragma unroll
    for (int o = 16; o > 0; o >>= 1) s += __shfl_down_sync(0xffffffffu, s, o);
    __shared__ float ws[8];
    if ((threadIdx.x & 31) == 0) ws[threadIdx.x >> 5] = s;
    __syncthreads();
    if (threadIdx.x == 0) {
        float t = 0.0f;
        #pragma unroll
        for (int i = 0; i < 8; i++) t += ws[i];
        g_partial[blk] = t;
    }
}

// --------------------- 2) routing softmax + kernel mix --------------------
__global__ void mix_kernel(const float* __restrict__ w_experts,
                           const float* __restrict__ fc_w,
                           const float* __restrict__ fc_b) {
    __shared__ float pooled_s[256];
    __shared__ float r_s[16][3];
    const int tid = threadIdx.x;

    pooled_s[tid] = (g_partial[tid * 4 + 0] + g_partial[tid * 4 + 1] +
                     g_partial[tid * 4 + 2] + g_partial[tid * 4 + 3]) * (1.0f / (float)HW);
    __syncthreads();

    if (tid < 16) {
        float lg[3];
        #pragma unroll
        for (int e = 0; e < 3; e++) {
            float a = fc_b[e];
            #pragma unroll
            for (int c = 0; c < 16; c++) a += pooled_s[tid * 16 + c] * fc_w[e * 16 + c];
            lg[e] = a;
        }
        float m = fmaxf(lg[0], fmaxf(lg[1], lg[2]));
        float ex0 = expf(lg[0] - m), ex1 = expf(lg[1] - m), ex2 = expf(lg[2] - m);
        float inv = 1.0f / (ex0 + ex1 + ex2);
        r_s[tid][0] = ex0 * inv;
        r_s[tid][1] = ex1 * inv;
        r_s[tid][2] = ex2 * inv;
    }
    __syncthreads();

    for (int i = tid; i < 36864; i += 256) {
        int b    = i / 2304;
        int rem  = i - b * 2304;
        int c    = rem / 144;
        int rem2 = rem - c * 144;
        int tap  = rem2 >> 4;
        int oc   = rem2 & 15;
        float v = 0.0f;
        #pragma unroll
        for (int e = 0; e < 3; e++)
            v += r_s[b][e] * w_experts[((e * 16 + oc) * 16 + c) * 9 + tap];
        g_wmix[i] = v;
    }
}

// ------------------------------ 3) conv -----------------------------------
typedef unsigned long long u64;

__device__ __forceinline__ void ffma2(u64& d, u64 a, u64 b) {
    asm("fma.rn.f32x2 %0, %1, %2, %0;" : "+l"(d) : "l"(a), "l"(b));
}
__device__ __forceinline__ u64 pack2(float v) {
    u64 r;
    asm("mov.b64 %0, {%1, %1};" : "=l"(r) : "f"(v));
    return r;
}
__device__ __forceinline__ void unpack2(float& lo, float& hi, u64 v) {
    asm("mov.b64 {%0, %1}, %2;" : "=f"(lo), "=f"(hi) : "l"(v));
}

__global__ void __launch_bounds__(256, 2)
conv_kernel(const float* __restrict__ x, const float* __restrict__ bias,
            float* __restrict__ out) {
    extern __shared__ float smem[];
    float* in_s = smem;                 // 16 * 1224 = 19584 floats
    float* w_s  = smem + 19584;         // 2304 floats
    float* b_s  = w_s + 2304;           // 16 floats

    const int tid = threadIdx.x;
    const int b   = blockIdx.z;
    const int x0  = blockIdx.x * 64;
    const int y0  = blockIdx.y * 16;

    for (int i = tid; i < 2304; i += 256) w_s[i] = g_wmix[b * 2304 + i];
    if (tid < 16) b_s[tid] = bias[tid];

    const float* xb = x + (size_t)b * 16 * HW;
    for (int i = tid; i < 19008; i += 256) {       // 16 * 18 * 66
        int c   = i / 1188;
        int rem = i - c * 1188;
        int row = rem / 66;
        int col = rem - row * 66;
        int gy = y0 + row - 1; gy = gy < 0 ? -gy : (gy > 511 ? 1022 - gy : gy);
        int gx = x0 + col - 1; gx = gx < 0 ? -gx : (gx > 511 ? 1022 - gx : gx);
        in_s[c * 1224 + row * 68 + col] = xb[(c << 18) + (gy << 9) + gx];
    }
    __syncthreads();

    const int tx = (tid & 15) << 2;     // 0,4,...,60
    const int ty = tid >> 4;            // 0..15

    // acc2[px][op]: lanes = (oc=2*op, oc=2*op+1) for pixel tx+px
    u64 acc2[4][8];
    {
        const u64* bp = reinterpret_cast<const u64*>(b_s);
        #pragma unroll
        for (int op = 0; op < 8; op++) {
            u64 bv = bp[op];
            acc2[0][op] = bv; acc2[1][op] = bv; acc2[2][op] = bv; acc2[3][op] = bv;
        }
    }

    const float* ip = in_s + ty * 68 + tx;

    #pragma unroll 1
    for (int c = 0; c < 16; c++) {
        float r[3][6];
        #pragma unroll
        for (int dy = 0; dy < 3; dy++) {
            const float* rp = ip + c * 1224 + dy * 68;
            float4 v4 = *reinterpret_cast<const float4*>(rp);
            float2 v2 = *reinterpret_cast<const float2*>(rp + 4);
            r[dy][0] = v4.x; r[dy][1] = v4.y; r[dy][2] = v4.z; r[dy][3] = v4.w;
            r[dy][4] = v2.x; r[dy][5] = v2.y;
        }
        const u64* wc = reinterpret_cast<const u64*>(w_s + c * 144);
        #pragma unroll
        for (int dy = 0; dy < 3; dy++) {
            #pragma unroll
            for (int dx = 0; dx < 3; dx++) {
                const u64* wt = wc + (dy * 3 + dx) * 8;   // 8 u64 = 16 oc
                u64 p0 = pack2(r[dy][dx + 0]);
                u64 p1 = pack2(r[dy][dx + 1]);
                u64 p2 = pack2(r[dy][dx + 2]);
                u64 p3 = pack2(r[dy][dx + 3]);
                #pragma unroll
                for (int op = 0; op < 8; op++) {
                    u64 w2 = wt[op];
                    ffma2(acc2[0][op], p0, w2);
                    ffma2(acc2[1][op], p1, w2);
                    ffma2(acc2[2][op], p2, w2);
                    ffma2(acc2[3][op], p3, w2);
                }
            }
        }
    }

    float* op_base = out + (size_t)(b * 16) * HW + ((y0 + ty) << 9) + x0 + tx;
    #pragma unroll
    for (int op = 0; op < 8; op++) {
        float v0l, v0h, v1l, v1h, v2l, v2h, v3l, v3h;
        unpack2(v0l, v0h, acc2[0][op]);
        unpack2(v1l, v1h, acc2[1][op]);
        unpack2(v2l, v2h, acc2[2][op]);
        unpack2(v3l, v3h, acc2[3][op]);
        *reinterpret_cast<float4*>(op_base + ((size_t)(2 * op)     << 18)) =
            make_float4(v0l, v1l, v2l, v3l);
        *reinterpret_cast<float4*>(op_base + ((size_t)(2 * op + 1) << 18)) =
            make_float4(v0h, v1h, v2h, v3h);
    }
}

// ---------------------------------------------------------------------------
extern "C" void kernel_launch(void* const* d_in, const int* in_sizes, int n_in,
                              void* d_out, int out_size) {
    const float* x         = (const float*)d_in[0];
    const float* w_experts = (const float*)d_in[1];
    const float* bias      = (const float*)d_in[2];
    const float* fc_w      = (const float*)d_in[3];
    const float* fc_b      = (const float*)d_in[4];
    float* out = (float*)d_out;

    const int smem_bytes = (19584 + 2304 + 16) * 4;
    cudaFuncSetAttribute(conv_kernel, cudaFuncAttributeMaxDynamicSharedMemorySize, smem_bytes);

    pool_kernel<<<1024, 256>>>(x);
    mix_kernel<<<1, 256>>>(w_experts, fc_w, fc_b);
    conv_kernel<<<dim3(8, 32, 16), 256, smem_bytes>>>(x, bias, out);
}